// round 9
// baseline (speedup 1.0000x reference)
#include <cuda_runtime.h>
#include <cuda_fp16.h>
#include <cstdint>

#define BATCH 256
#define S2    32768
#define HID   512
#define HEADS 1024

// ---------------- scratch ----------------
__device__ float g_cxpre[BATCH * HID];
__device__ float g_cx[BATCH];
__device__ float g_x1[BATCH * 2 * HID];
__device__ float g_x2[BATCH * HID];
__device__ float g_x3[BATCH * HEADS];
// pre-split A (hi/lo fp16, values bitwise-identical to in-kernel split4h(x*256))
__device__ __half g_Ahi[BATCH * S2];
__device__ __half g_Alo[BATCH * S2];

#define SCALE_A 256.0f
#define SCALE_W 4096.0f
#define INV_SCALE (1.0f / (256.0f * 4096.0f))

__device__ __forceinline__ void split4h(float4 v, float sc,
                                        uint32_t& h0, uint32_t& h1,
                                        uint32_t& l0, uint32_t& l1) {
    float x = v.x * sc, y = v.y * sc, z = v.z * sc, w = v.w * sc;
    __half2 a01 = __floats2half2_rn(x, y);
    __half2 a23 = __floats2half2_rn(z, w);
    float2 f01 = __half22float2(a01);
    float2 f23 = __half22float2(a23);
    __half2 r01 = __floats2half2_rn(x - f01.x, y - f01.y);
    __half2 r23 = __floats2half2_rn(z - f23.x, w - f23.y);
    h0 = *reinterpret_cast<uint32_t*>(&a01);
    h1 = *reinterpret_cast<uint32_t*>(&a23);
    l0 = *reinterpret_cast<uint32_t*>(&r01);
    l1 = *reinterpret_cast<uint32_t*>(&r23);
}

// ---------------- A pre-split: one float4 per thread ----------------
__global__ void conv_a_kernel(const float* __restrict__ A) {
    int i = blockIdx.x * 256 + threadIdx.x;          // 2M float4 groups
    float4 v = reinterpret_cast<const float4*>(A)[i];
    uint32_t h0, h1, l0, l1;
    split4h(v, SCALE_A, h0, h1, l0, l1);
    reinterpret_cast<uint2*>(g_Ahi)[i] = make_uint2(h0, h1);
    reinterpret_cast<uint2*>(g_Alo)[i] = make_uint2(l0, l1);
}

// ---------------- fused init ----------------
__global__ void init_all_kernel(const float* __restrict__ b_c1, const float* __restrict__ b1,
                                const float* __restrict__ b2, const float* __restrict__ b3,
                                float* __restrict__ out) {
    int i = blockIdx.x * 256 + threadIdx.x;
    if (i < 131072) {
        g_cxpre[i] = b_c1[i & 511];
    } else if (i < 393216) {
        int j = i - 131072; g_x1[j] = b1[j & 1023];
    } else if (i < 655360) {
        out[i - 393216] = 0.0f;
    } else if (i < 786432) {
        int j = i - 655360; g_x2[j] = b2[j & 511];
    } else {
        int j = i - 786432; g_x3[j] = b3[j & 1023];
    }
}

// ---------------- fp32 split-K GEMM (small layers) — R7 version, BM=64 ----------------
#define BM 64
#define BN 64
#define BKK 32
#define AS_STRIDE 33
#define WS_STRIDE 68

__global__ __launch_bounds__(256) void splitk_gemm(
    const float* __restrict__ A, const float* __restrict__ W,
    float* __restrict__ C, int M, int N, int K, int kchunk)
{
    __shared__ float As[BM * AS_STRIDE];
    __shared__ float Ws[BKK * WS_STRIDE];

    const int tid  = threadIdx.x;
    const int mbase = blockIdx.y * BM;
    const int nbase = blockIdx.x * BN;
    const int k0    = blockIdx.z * kchunk;

    const int lane = tid & 31, warp = tid >> 5;
    const int wm = warp & 3, wn = warp >> 2;
    const int m0 = wm * 16 + (lane >> 3) * 4;
    const int n0 = wn * 32 + (lane & 7) * 4;

    unsigned long long acc[4][2];
#pragma unroll
    for (int i = 0; i < 4; i++) { acc[i][0] = 0ull; acc[i][1] = 0ull; }

    for (int kk = k0; kk < k0 + kchunk; kk += BKK) {
#pragma unroll
        for (int l = 0; l < 2; l++) {
            int f   = tid + l * 256;
            int row = f >> 3;
            int kc  = (f & 7) * 4;
            float4 va = *reinterpret_cast<const float4*>(&A[(size_t)(mbase + row) * K + kk + kc]);
            As[row * AS_STRIDE + kc + 0] = va.x;
            As[row * AS_STRIDE + kc + 1] = va.y;
            As[row * AS_STRIDE + kc + 2] = va.z;
            As[row * AS_STRIDE + kc + 3] = va.w;
            float4 vw = *reinterpret_cast<const float4*>(&W[(size_t)(nbase + row) * K + kk + kc]);
            Ws[(kc + 0) * WS_STRIDE + row] = vw.x;
            Ws[(kc + 1) * WS_STRIDE + row] = vw.y;
            Ws[(kc + 2) * WS_STRIDE + row] = vw.z;
            Ws[(kc + 3) * WS_STRIDE + row] = vw.w;
        }
        __syncthreads();

#pragma unroll
        for (int k = 0; k < BKK; k++) {
            unsigned long long pa[4];
#pragma unroll
            for (int i = 0; i < 4; i++) {
                unsigned int au = __float_as_uint(As[(m0 + i) * AS_STRIDE + k]);
                asm("mov.b64 %0, {%1, %1};" : "=l"(pa[i]) : "r"(au));
            }
            unsigned long long w0 = *reinterpret_cast<const unsigned long long*>(&Ws[k * WS_STRIDE + n0]);
            unsigned long long w1 = *reinterpret_cast<const unsigned long long*>(&Ws[k * WS_STRIDE + n0 + 2]);
#pragma unroll
            for (int i = 0; i < 4; i++) {
                asm("fma.rn.f32x2 %0, %1, %2, %0;" : "+l"(acc[i][0]) : "l"(pa[i]), "l"(w0));
                asm("fma.rn.f32x2 %0, %1, %2, %0;" : "+l"(acc[i][1]) : "l"(pa[i]), "l"(w1));
            }
        }
        __syncthreads();
    }

#pragma unroll
    for (int i = 0; i < 4; i++) {
#pragma unroll
        for (int j = 0; j < 2; j++) {
            float lo = __uint_as_float((unsigned)(acc[i][j] & 0xffffffffull));
            float hi = __uint_as_float((unsigned)(acc[i][j] >> 32));
            size_t base = (size_t)(mbase + m0 + i) * N + nbase + n0 + 2 * j;
            atomicAdd(&C[base], lo);
            atomicAdd(&C[base + 1], hi);
        }
    }
}

// ============================================================================
// Big GEMMs via mma.sync fp16 hi/lo 3-product. Smem contents, MMA order and
// epilogue BITWISE IDENTICAL to round-7; only the A loader changed — it now
// copies pre-split fp16 (g_Ahi/g_Alo) instead of converting fp32 in-kernel.
// ============================================================================
#define GB_STRIDE 80
#define A_TILE   (128 * GB_STRIDE)
#define W_TILE   (64 * GB_STRIDE)
#define GB_BUF   (2 * A_TILE + 2 * W_TILE)
#define GB_NBUF  3
#define GB_SMEM  (GB_NBUF * GB_BUF)

__device__ __forceinline__ uint32_t smem_u32(const void* p) {
    uint32_t a;
    asm("{ .reg .u64 t; cvta.to.shared.u64 t, %1; cvt.u32.u64 %0, t; }" : "=r"(a) : "l"(p));
    return a;
}
__device__ __forceinline__ void ldsm_x4(uint32_t& r0, uint32_t& r1, uint32_t& r2,
                                        uint32_t& r3, uint32_t addr) {
    asm volatile("ldmatrix.sync.aligned.m8n8.x4.shared.b16 {%0,%1,%2,%3}, [%4];"
                 : "=r"(r0), "=r"(r1), "=r"(r2), "=r"(r3) : "r"(addr));
}
__device__ __forceinline__ void mma_f16(float* d, const uint32_t* a, const uint32_t* b) {
    asm volatile("mma.sync.aligned.m16n8k16.row.col.f32.f16.f16.f32 "
                 "{%0,%1,%2,%3}, {%4,%5,%6,%7}, {%8,%9}, {%0,%1,%2,%3};"
                 : "+f"(d[0]), "+f"(d[1]), "+f"(d[2]), "+f"(d[3])
                 : "r"(a[0]), "r"(a[1]), "r"(a[2]), "r"(a[3]), "r"(b[0]), "r"(b[1]));
}

struct GbRegs { uint4 Ah[4]; uint4 Al[4]; float4 Wr[4]; };

__device__ __forceinline__ void gb_ldg(GbRegs& R, const __half* ahB, const __half* alB,
                                       const float* wB, size_t kf) {
#pragma unroll
    for (int i = 0; i < 4; i++) {
        R.Ah[i] = *reinterpret_cast<const uint4*>(ahB + (size_t)(32 * i) * S2 + kf);
        R.Al[i] = *reinterpret_cast<const uint4*>(alB + (size_t)(32 * i) * S2 + kf);
    }
#pragma unroll
    for (int i = 0; i < 4; i++)
        R.Wr[i] = *reinterpret_cast<const float4*>(wB + (size_t)(16 * i) * S2 + kf);
}
__device__ __forceinline__ void gb_sts(const GbRegs& R, char* buf,
                                       int arow, int ag, int lrow, int lg) {
#pragma unroll
    for (int i = 0; i < 4; i++) {
        uint32_t off = (uint32_t)(arow + 32 * i) * GB_STRIDE + ag * 16;
        *reinterpret_cast<uint4*>(buf + off) = R.Ah[i];
        *reinterpret_cast<uint4*>(buf + A_TILE + off) = R.Al[i];
    }
#pragma unroll
    for (int i = 0; i < 4; i++) {
        uint32_t h0, h1, l0, l1;
        uint32_t off = (uint32_t)(lrow + 16 * i) * GB_STRIDE + lg * 8;
        split4h(R.Wr[i], SCALE_W, h0, h1, l0, l1);
        *reinterpret_cast<uint2*>(buf + 2 * A_TILE + off) = make_uint2(h0, h1);
        *reinterpret_cast<uint2*>(buf + 2 * A_TILE + W_TILE + off) = make_uint2(l0, l1);
    }
}

__global__ __launch_bounds__(128, 2) void big_gemm_hmma(
    const float* __restrict__ Wc1, const float* __restrict__ W1)
{
    extern __shared__ char smem[];
    const uint32_t sbase = smem_u32(smem);
    const int tid = threadIdx.x;
    const int lane = tid & 31, wm = tid >> 5;

    int b = blockIdx.x;
    int t = b / 6, z = b % 6;
    const float* W; float* C; int N, mt, nt;
    if (t < 16) { W = Wc1; C = g_cxpre; N = HID;     mt = t & 1; nt = t >> 1; }
    else { t -= 16; W = W1; C = g_x1;   N = 2 * HID; mt = t & 1; nt = t >> 1; }
    const int mbase = mt * 128, nbase = nt * 64;
    const int c0 = z * 1024 / 6, c1 = (z + 1) * 1024 / 6;
    const int n = c1 - c0;

    // A loader mapping: 128 threads -> 32 rows x 4 16B-groups (8 fp16 each)
    const int arow = tid >> 2;      // 0..31
    const int ag   = tid & 3;       // 0..3
    // W loader mapping (unchanged): 16 rows x 8 float4-groups
    const int lrow = tid >> 3;      // 0..15
    const int lg   = tid & 7;       // 0..7
    const __half* ahB = g_Ahi + (size_t)(mbase + arow) * S2 + ag * 8;
    const __half* alB = g_Alo + (size_t)(mbase + arow) * S2 + ag * 8;
    const float*  wB  = W + (size_t)(nbase + lrow) * S2 + lg * 4;

    float acc[2][8][4];
#pragma unroll
    for (int i = 0; i < 2; i++)
#pragma unroll
        for (int j = 0; j < 8; j++)
#pragma unroll
            for (int r = 0; r < 4; r++) acc[i][j][r] = 0.f;

    const uint32_t a_rel = (uint32_t)(wm * 32 + (lane & 15)) * GB_STRIDE + (lane >> 4) * 16;
    const uint32_t b_rel = 2 * A_TILE
                         + (uint32_t)((lane & 7) + ((lane >> 4) << 3)) * GB_STRIDE
                         + ((lane >> 3) & 1) * 16;

    GbRegs R;
    gb_ldg(R, ahB, alB, wB, (size_t)c0 * 32);
    gb_sts(R, smem + 0 * GB_BUF, arow, ag, lrow, lg);
    if (n > 1) gb_ldg(R, ahB, alB, wB, (size_t)(c0 + 1) * 32);
    __syncthreads();

    for (int li = 0; li < n; li++) {
        if (li + 1 < n) {
            gb_sts(R, smem + ((li + 1) % GB_NBUF) * GB_BUF, arow, ag, lrow, lg);
            if (li + 2 < n) gb_ldg(R, ahB, alB, wB, (size_t)(c0 + li + 2) * 32);
        }
        __syncthreads();

        const uint32_t bufb = sbase + (li % GB_NBUF) * GB_BUF;
        const uint32_t a_base = bufb + a_rel;
        const uint32_t b_base = bufb + b_rel;
#pragma unroll
        for (int ks = 0; ks < 2; ks++) {
            uint32_t af[2][2][4];
            uint32_t bf[2][8][2];
#pragma unroll
            for (int s = 0; s < 2; s++)
#pragma unroll
                for (int mi = 0; mi < 2; mi++)
                    ldsm_x4(af[s][mi][0], af[s][mi][1], af[s][mi][2], af[s][mi][3],
                            a_base + s * A_TILE + mi * (16 * GB_STRIDE) + ks * 32);
#pragma unroll
            for (int s = 0; s < 2; s++)
#pragma unroll
                for (int nj2 = 0; nj2 < 4; nj2++) {
                    uint32_t r0, r1, r2, r3;
                    ldsm_x4(r0, r1, r2, r3,
                            b_base + s * W_TILE + nj2 * (16 * GB_STRIDE) + ks * 32);
                    bf[s][nj2 * 2][0] = r0; bf[s][nj2 * 2][1] = r1;
                    bf[s][nj2 * 2 + 1][0] = r2; bf[s][nj2 * 2 + 1][1] = r3;
                }
#pragma unroll
            for (int mi = 0; mi < 2; mi++)
#pragma unroll
                for (int nj = 0; nj < 8; nj++) {
                    mma_f16(acc[mi][nj], af[0][mi], bf[0][nj]);
                    mma_f16(acc[mi][nj], af[0][mi], bf[1][nj]);
                    mma_f16(acc[mi][nj], af[1][mi], bf[0][nj]);
                }
        }
    }

#pragma unroll
    for (int mi = 0; mi < 2; mi++) {
        int row0 = mbase + wm * 32 + mi * 16 + (lane >> 2);
#pragma unroll
        for (int nj = 0; nj < 8; nj++) {
            int col = nbase + nj * 8 + (lane & 3) * 2;
            float* Cp = C + (size_t)row0 * N + col;
            atomicAdd(Cp,             acc[mi][nj][0] * INV_SCALE);
            atomicAdd(Cp + 1,         acc[mi][nj][1] * INV_SCALE);
            atomicAdd(Cp + 8 * N,     acc[mi][nj][2] * INV_SCALE);
            atomicAdd(Cp + 8 * N + 1, acc[mi][nj][3] * INV_SCALE);
        }
    }
}

// ============================================================================
// kWTA via exact radix-select (threshold value-identical to full sort).
// ============================================================================
__device__ __forceinline__ uint32_t f2u(float f) {
    uint32_t b = __float_as_uint(f);
    return (b & 0x80000000u) ? ~b : (b | 0x80000000u);
}
__device__ __forceinline__ float u2f(uint32_t u) {
    uint32_t b = (u & 0x80000000u) ? (u & 0x7fffffffu) : ~u;
    return __uint_as_float(b);
}

template <int NWID, int DO_CX>
__global__ __launch_bounds__(512) void kwta_radix(float* __restrict__ x,
                                                  const float* __restrict__ Wc2) {
    __shared__ uint32_t keys[NWID];
    __shared__ int hist[256];
    __shared__ uint32_t sh_prefix;
    __shared__ int sh_want;
    __shared__ int cnt_gt, cnt_eq;
    __shared__ float red[4];

    const int row = blockIdx.x;
    const int tid = threadIdx.x;
    float* xr = x + (size_t)row * NWID;

    if (DO_CX) {
        if (tid < 128) {
            float s = 0.f;
            for (int j = tid; j < HID; j += 128)
                s += tanhf(g_cxpre[row * HID + j]) * Wc2[j];
#pragma unroll
            for (int off = 16; off; off >>= 1) s += __shfl_xor_sync(0xffffffffu, s, off);
            if ((tid & 31) == 0) red[tid >> 5] = s;
        }
        __syncthreads();
        if (tid == 0) {
            float t = red[0] + red[1] + red[2] + red[3];
            g_cx[row] = 1.0f / (1.0f + expf(-t));
        }
        __syncthreads();
    }

    for (int i = tid; i < NWID; i += 512) keys[i] = f2u(xr[i]);
    const int k = (int)(g_cx[row] * (float)NWID);
    if (tid == 0) { sh_prefix = 0u; sh_want = k; cnt_gt = 0; cnt_eq = 0; }
    __syncthreads();

    if (k <= 0) {
        for (int i = tid; i < NWID; i += 512) xr[i] = 0.f;
        return;
    }
    if (k >= NWID) return;

#pragma unroll
    for (int pass = 0; pass < 4; pass++) {
        const int shift = 24 - 8 * pass;
        if (tid < 256) hist[tid] = 0;
        __syncthreads();
        const uint32_t pref = sh_prefix;
        const int want = sh_want;
        const uint32_t maskhi = (pass == 0) ? 0u : (0xffffffffu << (shift + 8));
        for (int i = tid; i < NWID; i += 512) {
            uint32_t key = keys[i];
            if ((key & maskhi) == pref)
                atomicAdd(&hist[(key >> shift) & 255], 1);
        }
        __syncthreads();
        if (tid < 32) {
            int h[8], part = 0;
#pragma unroll
            for (int j = 0; j < 8; j++) { h[j] = hist[tid * 8 + j]; part += h[j]; }
            int suf = part;
#pragma unroll
            for (int off = 1; off < 32; off <<= 1) {
                int tt = __shfl_down_sync(0xffffffffu, suf, off);
                if (tid + off < 32) suf += tt;
            }
            int above = suf - part;
            if (above < want && want <= suf) {
                int run = above;
#pragma unroll
                for (int j = 7; j >= 0; j--) {
                    run += h[j];
                    if (run >= want) {
                        sh_prefix = pref | ((uint32_t)(tid * 8 + j) << shift);
                        sh_want = want - (run - h[j]);
                        break;
                    }
                }
            }
        }
        __syncthreads();
    }

    const float T = u2f(sh_prefix);

    int lg_ = 0, le_ = 0;
    for (int i = tid; i < NWID; i += 512) {
        float v = u2f(keys[i]);
        if (v > T) lg_++;
        else if (v == T) le_++;
    }
    atomicAdd(&cnt_gt, lg_);
    atomicAdd(&cnt_eq, le_);
    __syncthreads();
    const int r = k - cnt_gt;

    for (int i = tid; i < NWID; i += 512) {
        float v = u2f(keys[i]);
        if (v < T) xr[i] = 0.f;
    }
    __syncthreads();

    if (cnt_eq != r) {
        if (tid == 0) {
            int rr = r;
            for (int i = 0; i < NWID; i++) {
                if (u2f(keys[i]) == T) {
                    if (rr > 0) rr--;
                    else xr[i] = 0.f;
                }
            }
        }
    }
}

// ---------------- launch ----------------
extern "C" void kernel_launch(void* const* d_in, const int* in_sizes, int n_in,
                              void* d_out, int out_size) {
    const float* input = (const float*)d_in[0];
    const float* W_c1  = (const float*)d_in[1];
    const float* b_c1  = (const float*)d_in[2];
    const float* W_c2  = (const float*)d_in[3];
    const float* W1    = (const float*)d_in[4];
    const float* b1    = (const float*)d_in[5];
    const float* W2    = (const float*)d_in[6];
    const float* b2    = (const float*)d_in[7];
    const float* W3    = (const float*)d_in[8];
    const float* b3    = (const float*)d_in[9];
    const float* W4    = (const float*)d_in[10];
    float* out = (float*)d_out;

    float *x1, *x2, *x3;
    cudaGetSymbolAddress((void**)&x1, g_x1);
    cudaGetSymbolAddress((void**)&x2, g_x2);
    cudaGetSymbolAddress((void**)&x3, g_x3);

    cudaFuncSetAttribute(big_gemm_hmma, cudaFuncAttributeMaxDynamicSharedMemorySize, GB_SMEM);

    // A pre-split (bitwise-identical hi/lo fp16) + accumulator inits
    conv_a_kernel<<<8192, 256>>>(input);
    init_all_kernel<<<4096, 256>>>(b_c1, b1, b2, b3, out);

    big_gemm_hmma<<<288, 128, GB_SMEM>>>(W_c1, W1);

    kwta_radix<2 * HID, 1><<<BATCH, 512>>>(x1, W_c2);

    {
        dim3 g(HID / BN, BATCH / BM, 4);
        splitk_gemm<<<g, 256>>>(x1, W2, x2, BATCH, HID, 2 * HID, (2 * HID) / 4);
    }
    kwta_radix<HID, 0><<<BATCH, 512>>>(x2, nullptr);

    {
        dim3 g(HEADS / BN, BATCH / BM, 2);
        splitk_gemm<<<g, 256>>>(x2, W3, x3, BATCH, HEADS, HID, HID / 2);
    }
    kwta_radix<HEADS, 0><<<BATCH, 512>>>(x3, nullptr);

    {
        dim3 g(HEADS / BN, BATCH / BM, 4);
        splitk_gemm<<<g, 256>>>(x3, W4, out, BATCH, HEADS, HEADS, HEADS / 4);
    }
}

// round 10
// speedup vs baseline: 1.0942x; 1.0942x over previous
#include <cuda_runtime.h>
#include <cuda_fp16.h>
#include <cstdint>

#define BATCH 256
#define S2    32768
#define HID   512
#define HEADS 1024

// ---------------- scratch ----------------
__device__ float g_cxpre[BATCH * HID];
__device__ float g_cx[BATCH];
__device__ float g_x1[BATCH * 2 * HID];
__device__ float g_x2[BATCH * HID];
__device__ float g_x3[BATCH * HEADS];

// ---------------- fused init ----------------
__global__ void init_all_kernel(const float* __restrict__ b_c1, const float* __restrict__ b1,
                                const float* __restrict__ b2, const float* __restrict__ b3,
                                float* __restrict__ out) {
    int i = blockIdx.x * 256 + threadIdx.x;
    if (i < 131072) {
        g_cxpre[i] = b_c1[i & 511];
    } else if (i < 393216) {
        int j = i - 131072; g_x1[j] = b1[j & 1023];
    } else if (i < 655360) {
        out[i - 393216] = 0.0f;
    } else if (i < 786432) {
        int j = i - 655360; g_x2[j] = b2[j & 511];
    } else {
        int j = i - 786432; g_x3[j] = b3[j & 1023];
    }
}

// ---------------- fp32 split-K GEMM (small layers) ----------------
// R7 numerics (BM=64, same k order / FFMA2 pairing / atomic combine).
// Only change: next gmem tile is prefetched into registers right after the
// first sync, overlapping DRAM latency with the current tile's compute.
#define BM 64
#define BN 64
#define BKK 32
#define AS_STRIDE 33
#define WS_STRIDE 68

__global__ __launch_bounds__(256) void splitk_gemm(
    const float* __restrict__ A, const float* __restrict__ W,
    float* __restrict__ C, int M, int N, int K, int kchunk)
{
    __shared__ float As[BM * AS_STRIDE];
    __shared__ float Ws[BKK * WS_STRIDE];

    const int tid  = threadIdx.x;
    const int mbase = blockIdx.y * BM;
    const int nbase = blockIdx.x * BN;
    const int k0    = blockIdx.z * kchunk;

    const int lane = tid & 31, warp = tid >> 5;
    const int wm = warp & 3, wn = warp >> 2;
    const int m0 = wm * 16 + (lane >> 3) * 4;
    const int n0 = wn * 32 + (lane & 7) * 4;

    // loader per-thread row/k offsets
    const int row0 = tid >> 3,        kc0 = (tid & 7) * 4;          // l=0
    const int row1 = (tid + 256) >> 3, kc1 = ((tid + 256) & 7) * 4; // l=1

    unsigned long long acc[4][2];
#pragma unroll
    for (int i = 0; i < 4; i++) { acc[i][0] = 0ull; acc[i][1] = 0ull; }

    float4 va[2], vw[2];
    // prefetch first tile
    va[0] = *reinterpret_cast<const float4*>(&A[(size_t)(mbase + row0) * K + k0 + kc0]);
    vw[0] = *reinterpret_cast<const float4*>(&W[(size_t)(nbase + row0) * K + k0 + kc0]);
    va[1] = *reinterpret_cast<const float4*>(&A[(size_t)(mbase + row1) * K + k0 + kc1]);
    vw[1] = *reinterpret_cast<const float4*>(&W[(size_t)(nbase + row1) * K + k0 + kc1]);

    for (int kk = k0; kk < k0 + kchunk; kk += BKK) {
        // stage current tile to smem
        As[row0 * AS_STRIDE + kc0 + 0] = va[0].x;
        As[row0 * AS_STRIDE + kc0 + 1] = va[0].y;
        As[row0 * AS_STRIDE + kc0 + 2] = va[0].z;
        As[row0 * AS_STRIDE + kc0 + 3] = va[0].w;
        Ws[(kc0 + 0) * WS_STRIDE + row0] = vw[0].x;
        Ws[(kc0 + 1) * WS_STRIDE + row0] = vw[0].y;
        Ws[(kc0 + 2) * WS_STRIDE + row0] = vw[0].z;
        Ws[(kc0 + 3) * WS_STRIDE + row0] = vw[0].w;
        As[row1 * AS_STRIDE + kc1 + 0] = va[1].x;
        As[row1 * AS_STRIDE + kc1 + 1] = va[1].y;
        As[row1 * AS_STRIDE + kc1 + 2] = va[1].z;
        As[row1 * AS_STRIDE + kc1 + 3] = va[1].w;
        Ws[(kc1 + 0) * WS_STRIDE + row1] = vw[1].x;
        Ws[(kc1 + 1) * WS_STRIDE + row1] = vw[1].y;
        Ws[(kc1 + 2) * WS_STRIDE + row1] = vw[1].z;
        Ws[(kc1 + 3) * WS_STRIDE + row1] = vw[1].w;
        __syncthreads();

        // prefetch next tile (overlaps compute below)
        if (kk + BKK < k0 + kchunk) {
            const int kn = kk + BKK;
            va[0] = *reinterpret_cast<const float4*>(&A[(size_t)(mbase + row0) * K + kn + kc0]);
            vw[0] = *reinterpret_cast<const float4*>(&W[(size_t)(nbase + row0) * K + kn + kc0]);
            va[1] = *reinterpret_cast<const float4*>(&A[(size_t)(mbase + row1) * K + kn + kc1]);
            vw[1] = *reinterpret_cast<const float4*>(&W[(size_t)(nbase + row1) * K + kn + kc1]);
        }

#pragma unroll
        for (int k = 0; k < BKK; k++) {
            unsigned long long pa[4];
#pragma unroll
            for (int i = 0; i < 4; i++) {
                unsigned int au = __float_as_uint(As[(m0 + i) * AS_STRIDE + k]);
                asm("mov.b64 %0, {%1, %1};" : "=l"(pa[i]) : "r"(au));
            }
            unsigned long long w0 = *reinterpret_cast<const unsigned long long*>(&Ws[k * WS_STRIDE + n0]);
            unsigned long long w1 = *reinterpret_cast<const unsigned long long*>(&Ws[k * WS_STRIDE + n0 + 2]);
#pragma unroll
            for (int i = 0; i < 4; i++) {
                asm("fma.rn.f32x2 %0, %1, %2, %0;" : "+l"(acc[i][0]) : "l"(pa[i]), "l"(w0));
                asm("fma.rn.f32x2 %0, %1, %2, %0;" : "+l"(acc[i][1]) : "l"(pa[i]), "l"(w1));
            }
        }
        __syncthreads();
    }

#pragma unroll
    for (int i = 0; i < 4; i++) {
#pragma unroll
        for (int j = 0; j < 2; j++) {
            float lo = __uint_as_float((unsigned)(acc[i][j] & 0xffffffffull));
            float hi = __uint_as_float((unsigned)(acc[i][j] >> 32));
            size_t base = (size_t)(mbase + m0 + i) * N + nbase + n0 + 2 * j;
            atomicAdd(&C[base], lo);
            atomicAdd(&C[base + 1], hi);
        }
    }
}

// ============================================================================
// Big GEMMs via mma.sync fp16 hi/lo 3-product. BYTE-IDENTICAL to round-7.
// ============================================================================
#define GB_STRIDE 80
#define A_TILE   (128 * GB_STRIDE)
#define W_TILE   (64 * GB_STRIDE)
#define GB_BUF   (2 * A_TILE + 2 * W_TILE)
#define GB_NBUF  3
#define GB_SMEM  (GB_NBUF * GB_BUF)
#define SCALE_A 256.0f
#define SCALE_W 4096.0f
#define INV_SCALE (1.0f / (256.0f * 4096.0f))

__device__ __forceinline__ uint32_t smem_u32(const void* p) {
    uint32_t a;
    asm("{ .reg .u64 t; cvta.to.shared.u64 t, %1; cvt.u32.u64 %0, t; }" : "=r"(a) : "l"(p));
    return a;
}
__device__ __forceinline__ void ldsm_x4(uint32_t& r0, uint32_t& r1, uint32_t& r2,
                                        uint32_t& r3, uint32_t addr) {
    asm volatile("ldmatrix.sync.aligned.m8n8.x4.shared.b16 {%0,%1,%2,%3}, [%4];"
                 : "=r"(r0), "=r"(r1), "=r"(r2), "=r"(r3) : "r"(addr));
}
__device__ __forceinline__ void mma_f16(float* d, const uint32_t* a, const uint32_t* b) {
    asm volatile("mma.sync.aligned.m16n8k16.row.col.f32.f16.f16.f32 "
                 "{%0,%1,%2,%3}, {%4,%5,%6,%7}, {%8,%9}, {%0,%1,%2,%3};"
                 : "+f"(d[0]), "+f"(d[1]), "+f"(d[2]), "+f"(d[3])
                 : "r"(a[0]), "r"(a[1]), "r"(a[2]), "r"(a[3]), "r"(b[0]), "r"(b[1]));
}
__device__ __forceinline__ void split4h(float4 v, float sc,
                                        uint32_t& h0, uint32_t& h1,
                                        uint32_t& l0, uint32_t& l1) {
    float x = v.x * sc, y = v.y * sc, z = v.z * sc, w = v.w * sc;
    __half2 a01 = __floats2half2_rn(x, y);
    __half2 a23 = __floats2half2_rn(z, w);
    float2 f01 = __half22float2(a01);
    float2 f23 = __half22float2(a23);
    __half2 r01 = __floats2half2_rn(x - f01.x, y - f01.y);
    __half2 r23 = __floats2half2_rn(z - f23.x, w - f23.y);
    h0 = *reinterpret_cast<uint32_t*>(&a01);
    h1 = *reinterpret_cast<uint32_t*>(&a23);
    l0 = *reinterpret_cast<uint32_t*>(&r01);
    l1 = *reinterpret_cast<uint32_t*>(&r23);
}

struct GbRegs { float4 Ar[8]; float4 Wr[4]; };

__device__ __forceinline__ void gb_ldg(GbRegs& R, const float* aB, const float* wB, size_t kf) {
#pragma unroll
    for (int i = 0; i < 8; i++)
        R.Ar[i] = *reinterpret_cast<const float4*>(aB + (size_t)(16 * i) * S2 + kf);
#pragma unroll
    for (int i = 0; i < 4; i++)
        R.Wr[i] = *reinterpret_cast<const float4*>(wB + (size_t)(16 * i) * S2 + kf);
}
__device__ __forceinline__ void gb_sts(const GbRegs& R, char* buf, int lrow, int lg) {
#pragma unroll
    for (int i = 0; i < 8; i++) {
        uint32_t h0, h1, l0, l1;
        uint32_t off = (uint32_t)(lrow + 16 * i) * GB_STRIDE + lg * 8;
        split4h(R.Ar[i], SCALE_A, h0, h1, l0, l1);
        *reinterpret_cast<uint2*>(buf + off) = make_uint2(h0, h1);
        *reinterpret_cast<uint2*>(buf + A_TILE + off) = make_uint2(l0, l1);
    }
#pragma unroll
    for (int i = 0; i < 4; i++) {
        uint32_t h0, h1, l0, l1;
        uint32_t off = (uint32_t)(lrow + 16 * i) * GB_STRIDE + lg * 8;
        split4h(R.Wr[i], SCALE_W, h0, h1, l0, l1);
        *reinterpret_cast<uint2*>(buf + 2 * A_TILE + off) = make_uint2(h0, h1);
        *reinterpret_cast<uint2*>(buf + 2 * A_TILE + W_TILE + off) = make_uint2(l0, l1);
    }
}

__global__ __launch_bounds__(128, 2) void big_gemm_hmma(
    const float* __restrict__ A,
    const float* __restrict__ Wc1, const float* __restrict__ W1)
{
    extern __shared__ char smem[];
    const uint32_t sbase = smem_u32(smem);
    const int tid = threadIdx.x;
    const int lane = tid & 31, wm = tid >> 5;

    int b = blockIdx.x;
    int t = b / 6, z = b % 6;
    const float* W; float* C; int N, mt, nt;
    if (t < 16) { W = Wc1; C = g_cxpre; N = HID;     mt = t & 1; nt = t >> 1; }
    else { t -= 16; W = W1; C = g_x1;   N = 2 * HID; mt = t & 1; nt = t >> 1; }
    const int mbase = mt * 128, nbase = nt * 64;
    const int c0 = z * 1024 / 6, c1 = (z + 1) * 1024 / 6;
    const int n = c1 - c0;

    const int lrow = tid >> 3;
    const int lg   = tid & 7;
    const float* aB = A + (size_t)(mbase + lrow) * S2 + lg * 4;
    const float* wB = W + (size_t)(nbase + lrow) * S2 + lg * 4;

    float acc[2][8][4];
#pragma unroll
    for (int i = 0; i < 2; i++)
#pragma unroll
        for (int j = 0; j < 8; j++)
#pragma unroll
            for (int r = 0; r < 4; r++) acc[i][j][r] = 0.f;

    const uint32_t a_rel = (uint32_t)(wm * 32 + (lane & 15)) * GB_STRIDE + (lane >> 4) * 16;
    const uint32_t b_rel = 2 * A_TILE
                         + (uint32_t)((lane & 7) + ((lane >> 4) << 3)) * GB_STRIDE
                         + ((lane >> 3) & 1) * 16;

    GbRegs R;
    gb_ldg(R, aB, wB, (size_t)c0 * 32);
    gb_sts(R, smem + 0 * GB_BUF, lrow, lg);
    if (n > 1) gb_ldg(R, aB, wB, (size_t)(c0 + 1) * 32);
    __syncthreads();

    for (int li = 0; li < n; li++) {
        if (li + 1 < n) {
            gb_sts(R, smem + ((li + 1) % GB_NBUF) * GB_BUF, lrow, lg);
            if (li + 2 < n) gb_ldg(R, aB, wB, (size_t)(c0 + li + 2) * 32);
        }
        __syncthreads();

        const uint32_t bufb = sbase + (li % GB_NBUF) * GB_BUF;
        const uint32_t a_base = bufb + a_rel;
        const uint32_t b_base = bufb + b_rel;
#pragma unroll
        for (int ks = 0; ks < 2; ks++) {
            uint32_t af[2][2][4];
            uint32_t bf[2][8][2];
#pragma unroll
            for (int s = 0; s < 2; s++)
#pragma unroll
                for (int mi = 0; mi < 2; mi++)
                    ldsm_x4(af[s][mi][0], af[s][mi][1], af[s][mi][2], af[s][mi][3],
                            a_base + s * A_TILE + mi * (16 * GB_STRIDE) + ks * 32);
#pragma unroll
            for (int s = 0; s < 2; s++)
#pragma unroll
                for (int nj2 = 0; nj2 < 4; nj2++) {
                    uint32_t r0, r1, r2, r3;
                    ldsm_x4(r0, r1, r2, r3,
                            b_base + s * W_TILE + nj2 * (16 * GB_STRIDE) + ks * 32);
                    bf[s][nj2 * 2][0] = r0; bf[s][nj2 * 2][1] = r1;
                    bf[s][nj2 * 2 + 1][0] = r2; bf[s][nj2 * 2 + 1][1] = r3;
                }
#pragma unroll
            for (int mi = 0; mi < 2; mi++)
#pragma unroll
                for (int nj = 0; nj < 8; nj++) {
                    mma_f16(acc[mi][nj], af[0][mi], bf[0][nj]);
                    mma_f16(acc[mi][nj], af[0][mi], bf[1][nj]);
                    mma_f16(acc[mi][nj], af[1][mi], bf[0][nj]);
                }
        }
    }

#pragma unroll
    for (int mi = 0; mi < 2; mi++) {
        int row0 = mbase + wm * 32 + mi * 16 + (lane >> 2);
#pragma unroll
        for (int nj = 0; nj < 8; nj++) {
            int col = nbase + nj * 8 + (lane & 3) * 2;
            float* Cp = C + (size_t)row0 * N + col;
            atomicAdd(Cp,             acc[mi][nj][0] * INV_SCALE);
            atomicAdd(Cp + 1,         acc[mi][nj][1] * INV_SCALE);
            atomicAdd(Cp + 8 * N,     acc[mi][nj][2] * INV_SCALE);
            atomicAdd(Cp + 8 * N + 1, acc[mi][nj][3] * INV_SCALE);
        }
    }
}

// ============================================================================
// kWTA via exact radix-select — BYTE-IDENTICAL to round-7.
// ============================================================================
__device__ __forceinline__ uint32_t f2u(float f) {
    uint32_t b = __float_as_uint(f);
    return (b & 0x80000000u) ? ~b : (b | 0x80000000u);
}
__device__ __forceinline__ float u2f(uint32_t u) {
    uint32_t b = (u & 0x80000000u) ? (u & 0x7fffffffu) : ~u;
    return __uint_as_float(b);
}

template <int NWID, int DO_CX>
__global__ __launch_bounds__(512) void kwta_radix(float* __restrict__ x,
                                                  const float* __restrict__ Wc2) {
    __shared__ uint32_t keys[NWID];
    __shared__ int hist[256];
    __shared__ uint32_t sh_prefix;
    __shared__ int sh_want;
    __shared__ int cnt_gt, cnt_eq;
    __shared__ float red[4];

    const int row = blockIdx.x;
    const int tid = threadIdx.x;
    float* xr = x + (size_t)row * NWID;

    if (DO_CX) {
        if (tid < 128) {
            float s = 0.f;
            for (int j = tid; j < HID; j += 128)
                s += tanhf(g_cxpre[row * HID + j]) * Wc2[j];
#pragma unroll
            for (int off = 16; off; off >>= 1) s += __shfl_xor_sync(0xffffffffu, s, off);
            if ((tid & 31) == 0) red[tid >> 5] = s;
        }
        __syncthreads();
        if (tid == 0) {
            float t = red[0] + red[1] + red[2] + red[3];
            g_cx[row] = 1.0f / (1.0f + expf(-t));
        }
        __syncthreads();
    }

    for (int i = tid; i < NWID; i += 512) keys[i] = f2u(xr[i]);
    const int k = (int)(g_cx[row] * (float)NWID);
    if (tid == 0) { sh_prefix = 0u; sh_want = k; cnt_gt = 0; cnt_eq = 0; }
    __syncthreads();

    if (k <= 0) {
        for (int i = tid; i < NWID; i += 512) xr[i] = 0.f;
        return;
    }
    if (k >= NWID) return;

#pragma unroll
    for (int pass = 0; pass < 4; pass++) {
        const int shift = 24 - 8 * pass;
        if (tid < 256) hist[tid] = 0;
        __syncthreads();
        const uint32_t pref = sh_prefix;
        const int want = sh_want;
        const uint32_t maskhi = (pass == 0) ? 0u : (0xffffffffu << (shift + 8));
        for (int i = tid; i < NWID; i += 512) {
            uint32_t key = keys[i];
            if ((key & maskhi) == pref)
                atomicAdd(&hist[(key >> shift) & 255], 1);
        }
        __syncthreads();
        if (tid < 32) {
            int h[8], part = 0;
#pragma unroll
            for (int j = 0; j < 8; j++) { h[j] = hist[tid * 8 + j]; part += h[j]; }
            int suf = part;
#pragma unroll
            for (int off = 1; off < 32; off <<= 1) {
                int tt = __shfl_down_sync(0xffffffffu, suf, off);
                if (tid + off < 32) suf += tt;
            }
            int above = suf - part;
            if (above < want && want <= suf) {
                int run = above;
#pragma unroll
                for (int j = 7; j >= 0; j--) {
                    run += h[j];
                    if (run >= want) {
                        sh_prefix = pref | ((uint32_t)(tid * 8 + j) << shift);
                        sh_want = want - (run - h[j]);
                        break;
                    }
                }
            }
        }
        __syncthreads();
    }

    const float T = u2f(sh_prefix);

    int lg_ = 0, le_ = 0;
    for (int i = tid; i < NWID; i += 512) {
        float v = u2f(keys[i]);
        if (v > T) lg_++;
        else if (v == T) le_++;
    }
    atomicAdd(&cnt_gt, lg_);
    atomicAdd(&cnt_eq, le_);
    __syncthreads();
    const int r = k - cnt_gt;

    for (int i = tid; i < NWID; i += 512) {
        float v = u2f(keys[i]);
        if (v < T) xr[i] = 0.f;
    }
    __syncthreads();

    if (cnt_eq != r) {
        if (tid == 0) {
            int rr = r;
            for (int i = 0; i < NWID; i++) {
                if (u2f(keys[i]) == T) {
                    if (rr > 0) rr--;
                    else xr[i] = 0.f;
                }
            }
        }
    }
}

// ---------------- launch ----------------
extern "C" void kernel_launch(void* const* d_in, const int* in_sizes, int n_in,
                              void* d_out, int out_size) {
    const float* input = (const float*)d_in[0];
    const float* W_c1  = (const float*)d_in[1];
    const float* b_c1  = (const float*)d_in[2];
    const float* W_c2  = (const float*)d_in[3];
    const float* W1    = (const float*)d_in[4];
    const float* b1    = (const float*)d_in[5];
    const float* W2    = (const float*)d_in[6];
    const float* b2    = (const float*)d_in[7];
    const float* W3    = (const float*)d_in[8];
    const float* b3    = (const float*)d_in[9];
    const float* W4    = (const float*)d_in[10];
    float* out = (float*)d_out;

    float *x1, *x2, *x3;
    cudaGetSymbolAddress((void**)&x1, g_x1);
    cudaGetSymbolAddress((void**)&x2, g_x2);
    cudaGetSymbolAddress((void**)&x3, g_x3);

    cudaFuncSetAttribute(big_gemm_hmma, cudaFuncAttributeMaxDynamicSharedMemorySize, GB_SMEM);

    init_all_kernel<<<4096, 256>>>(b_c1, b1, b2, b3, out);

    big_gemm_hmma<<<288, 128, GB_SMEM>>>(input, W_c1, W1);

    kwta_radix<2 * HID, 1><<<BATCH, 512>>>(x1, W_c2);

    {
        dim3 g(HID / BN, BATCH / BM, 4);
        splitk_gemm<<<g, 256>>>(x1, W2, x2, BATCH, HID, 2 * HID, (2 * HID) / 4);
    }
    kwta_radix<HID, 0><<<BATCH, 512>>>(x2, nullptr);

    {
        dim3 g(HEADS / BN, BATCH / BM, 2);
        splitk_gemm<<<g, 256>>>(x2, W3, x3, BATCH, HEADS, HID, HID / 2);
    }
    kwta_radix<HEADS, 0><<<BATCH, 512>>>(x3, nullptr);

    {
        dim3 g(HEADS / BN, BATCH / BM, 4);
        splitk_gemm<<<g, 256>>>(x3, W4, out, BATCH, HEADS, HEADS, HEADS / 4);
    }
}